// round 13
// baseline (speedup 1.0000x reference)
#include <cuda_runtime.h>
#include <math.h>

#define BB     2
#define NN     128
#define EB     160
#define DEPTHL 6
#define NHEADS 8
#define DH     64
#define INNERD 512
#define DIMF   128
#define NF     127
#define SCALE  0.125f  /* 64^-0.5 */

#define GRIDN  128
#define NTHR   512

typedef unsigned long long u64;

// ---------------- f32x2 helpers -----------------------------------------------
__device__ __forceinline__ u64 pk2(float x) {
    u64 r; asm("mov.b64 %0, {%1,%1};" : "=l"(r) : "f"(x)); return r;
}
__device__ __forceinline__ void fma2(u64 &d, u64 a, u64 b) {
    asm("fma.rn.f32x2 %0, %1, %2, %3;" : "=l"(d) : "l"(a), "l"(b), "l"(d));
}
__device__ __forceinline__ float2 upk(u64 v) {
    float2 f; asm("mov.b64 {%0,%1}, %2;" : "=f"(f.x), "=f"(f.y) : "l"(v)); return f;
}

// ---------------- scratch (static device globals; no allocation) --------------
__device__ float g_nodes[BB*NN*DIMF];
__device__ float g_edges[BB*NN*NN*3];
__device__ float g_q   [BB*NN*INNERD];
__device__ float g_kbe [BB*NN*INNERD];
__device__ float g_vbe [BB*NN*INNERD];
__device__ float g_ao  [BB*NN*INNERD];

__device__ unsigned g_cnt = 0;
__device__ unsigned g_gen = 0;

// ---------------- grid barrier (all GRIDN blocks resident) --------------------
__device__ __forceinline__ void gbar() {
    __syncthreads();
    if (threadIdx.x == 0) {
        volatile unsigned* vg = &g_gen;
        unsigned gen = *vg;
        __threadfence();
        if (atomicAdd(&g_cnt, 1u) == GRIDN - 1) {
            atomicExch(&g_cnt, 0u);
            __threadfence();
            atomicAdd(&g_gen, 1u);
        } else {
            while (*vg == gen) __nanosleep(32);
        }
        __threadfence();
    }
    __syncthreads();
}

// ---------------- warp helpers -------------------------------------------------
__device__ __forceinline__ float warp_sum(float v) {
    #pragma unroll
    for (int off = 16; off > 0; off >>= 1)
        v += __shfl_xor_sync(0xffffffffu, v, off);
    return v;
}
__device__ __forceinline__ float warp_max(float v) {
    #pragma unroll
    for (int off = 16; off > 0; off >>= 1)
        v = fmaxf(v, __shfl_xor_sync(0xffffffffu, v, off));
    return v;
}
__device__ __forceinline__ float gelu_exact(float u) {
    return 0.5f * u * (1.f + erff(u * 0.70710678118654752f));
}

#define RT_ROWS 16
#define ITILE 16
#define KV4   17
// B-phase pool: k 34816 + v 34816 + q 4096 + p2 16384 + qwe 192
//             + s_m 128 + s_s 128 + s_scp 384 + s_pv 8192 = 99136
#define POOL_BYTES 99328

// ================================================================================
__global__ void __launch_bounds__(NTHR, 1) k_net(
    const int* __restrict__ indices, const float* __restrict__ coords,
    const int* __restrict__ bonds,   const float* __restrict__ noise,
    const float* __restrict__ atom_emb,
    const float* __restrict__ ln1_g, const float* __restrict__ ln1_b,
    const float* __restrict__ Wq,  const float* __restrict__ bq,
    const float* __restrict__ Wkv, const float* __restrict__ bkv,
    const float* __restrict__ We_, const float* __restrict__ be,
    const float* __restrict__ Wo,  const float* __restrict__ bo,
    const float* __restrict__ Wg1,
    const float* __restrict__ ln2g, const float* __restrict__ ln2b,
    const float* __restrict__ W1,  const float* __restrict__ b1,
    const float* __restrict__ W2,  const float* __restrict__ b2,
    const float* __restrict__ Wg2,
    const float* __restrict__ Wlin, const float* __restrict__ blin,
    float* __restrict__ out)
{
    extern __shared__ __align__(16) char pool[];
    int bid = blockIdx.x, tid = threadIdx.x;
    int wid = tid >> 5, lane = tid & 31;

    // ---------------- phase 0: node init + edge zero ---------------------------
    {
        int idx = bid*NTHR + tid;
        if (idx < BB*NN*DIMF) {
            int f = idx & 127, bn = idx >> 7;
            g_nodes[idx] = (f < NF) ? atom_emb[indices[bn]*NF + f] : noise[0];
        }
        if (idx < (BB*NN*NN*3)/4)
            ((float4*)g_edges)[idx] = make_float4(0.f, 0.f, 0.f, 0.f);
    }
    gbar();

    // ---------------- phase 0b: edge scatter (block 0) -------------------------
    if (bid == 0) {
        int* sb = (int*)pool;
        for (int t = tid; t < EB*2; t += NTHR) sb[t] = bonds[t];
        __syncthreads();
        if (tid < EB) {
            int i = sb[2*tid], j = sb[2*tid+1];
            bool laterSame = false, revExists = false;
            #pragma unroll 4
            for (int e = 0; e < EB; e++) {
                int ie = sb[2*e], je = sb[2*e+1];
                if (e > tid && ie == i && je == j) laterSame = true;
                if (ie == j && je == i)            revExists = true;
            }
            bool w2 = !laterSame;
            bool w1 = !laterSame && !revExists;
            if (w1 || w2) {
                for (int b = 0; b < BB; b++) {
                    float d0 = coords[(b*NN+i)*3+0] - coords[(b*NN+j)*3+0];
                    float d1 = coords[(b*NN+i)*3+1] - coords[(b*NN+j)*3+1];
                    float d2 = coords[(b*NN+i)*3+2] - coords[(b*NN+j)*3+2];
                    if (w2) {
                        size_t o = ((size_t)(b*NN+j)*NN + i)*3;
                        g_edges[o+0] = -d0; g_edges[o+1] = -d1; g_edges[o+2] = -d2;
                    }
                    if (w1) {
                        size_t o = ((size_t)(b*NN+i)*NN + j)*3;
                        g_edges[o+0] = d0; g_edges[o+1] = d1; g_edges[o+2] = d2;
                    }
                }
            }
        }
    }
    gbar();

    // ---------------- layers ---------------------------------------------------
    for (int l = 0; l < DEPTHL; l++) {
        // ======== phase A: LN1 + Q/KV proj, f32x2 (blocks 0..95, 512 thr) ======
        {
            const float* ln_g  = ln1_g + l*DIMF;
            const float* ln_b  = ln1_b + l*DIMF;
            const float* Wq_l  = Wq  + (size_t)l*DIMF*INNERD;
            const float* bq_l  = bq  + (size_t)l*INNERD;
            const float* Wkv_l = Wkv + (size_t)l*DIMF*2*INNERD;
            const float* bkv_l = bkv + (size_t)l*2*INNERD;
            const float* be_l  = be  + (size_t)l*INNERD;

            if (bid < 96) {
                u64* s_xd = (u64*)pool;            // [128][16] dup, 16KB
                int rowTile = bid / 6, ct = bid % 6, r0 = rowTile * RT_ROWS;

                // LN: warp per row
                {
                    int r = wid;
                    float4 xv = *(const float4*)&g_nodes[(r0+r)*DIMF + lane*4];
                    float s = xv.x + xv.y + xv.z + xv.w;
                    float mean = warp_sum(s) * (1.f/DIMF);
                    float dx = xv.x-mean, dy = xv.y-mean, dz = xv.z-mean, dw = xv.w-mean;
                    float v = dx*dx + dy*dy + dz*dz + dw*dw;
                    float rstd = rsqrtf(warp_sum(v) * (1.f/DIMF) + 1e-5f);
                    #pragma unroll
                    for (int q = 0; q < 4; q++) {
                        int d = lane*4 + q;
                        float val = (q==0?dx:q==1?dy:q==2?dz:dw);
                        s_xd[d*16 + r] = pk2(val * rstd * __ldg(&ln_g[d]) + __ldg(&ln_b[d]));
                    }
                }
                __syncthreads();

                // projection: thread = 4 cols (2 f32x2 pairs) x 2 adjacent rows
                int quad = tid & 63;
                int rg   = tid >> 6;            // 0..7
                int col  = ct*256 + quad*4;
                int rA   = rg*2;

                const float* Wp;
                int stride, region, rcol;
                if (col < 512) { Wp = Wq_l + col; stride = INNERD; region = 0; rcol = col; }
                else {
                    int ck = col - 512;
                    Wp = Wkv_l + ck; stride = 2*INNERD;
                    if (ck < 512) { region = 1; rcol = ck; }
                    else          { region = 2; rcol = ck - 512; }
                }

                u64 aA0=0, aA1=0, aB0=0, aB1=0;
                const ulonglong2* xp = (const ulonglong2*)(s_xd + rA);
                #pragma unroll 16
                for (int d = 0; d < DIMF; d++) {
                    ulonglong2 w2 = __ldg((const ulonglong2*)(Wp + (size_t)d*stride));
                    ulonglong2 xAB = xp[d*8];            // {xA, xB} one LDS.128
                    fma2(aA0, w2.x, xAB.x); fma2(aA1, w2.y, xAB.x);
                    fma2(aB0, w2.x, xAB.y); fma2(aB1, w2.y, xAB.y);
                }

                float4 bias;
                if (region == 0) bias = __ldg((const float4*)(bq_l + rcol));
                else {
                    float4 bk = __ldg((const float4*)(bkv_l + (region==1 ? rcol : rcol+512)));
                    float4 bv = __ldg((const float4*)(be_l + rcol));
                    bias = make_float4(bk.x+bv.x, bk.y+bv.y, bk.z+bv.z, bk.w+bv.w);
                }
                float* dst = (region==0) ? g_q : (region==1) ? g_kbe : g_vbe;
                float2 fA0 = upk(aA0), fA1 = upk(aA1), fB0 = upk(aB0), fB1 = upk(aB1);
                float4 oA = make_float4(fA0.x+bias.x, fA0.y+bias.y, fA1.x+bias.z, fA1.y+bias.w);
                float4 oB = make_float4(fB0.x+bias.x, fB0.y+bias.y, fB1.x+bias.z, fB1.y+bias.w);
                *(float4*)&dst[(size_t)(r0+rA  )*INNERD + rcol] = oA;
                *(float4*)&dst[(size_t)(r0+rA+1)*INNERD + rcol] = oB;
            }
        }
        gbar();

        // ======== phase B: attention (all 128 blocks, 512 thr) =================
        {
            const float* We_l = We_ + (size_t)l*3*INNERD;
            float4* s_k4  = (float4*)pool;               // [128][17]
            float4* s_v4  = s_k4 + NN*KV4;
            float4* s_q4  = s_v4 + NN*KV4;               // [16][16]
            u64*    s_p2  = (u64*)(s_q4 + ITILE*16);     // [16][128] unnorm exp
            float*  s_qwe = (float*)(s_p2 + ITILE*NN);   // [16][3]
            float*  s_m   = s_qwe + 48;                  // [16][2]
            float*  s_s   = s_m + 32;                    // [16][2]
            float*  s_scp = s_s + 32;                    // [16][2][3]
            float4* s_pv  = (float4*)(s_scp + 96);       // [2jh][8rp][2row][16d4]

            int b  = bid >> 6;
            int h  = (bid >> 3) & 7;
            int it = bid & 7;

            for (int idx = tid; idx < NN*16; idx += NTHR) {
                int j = idx >> 4, d4i = idx & 15;
                size_t goff = ((size_t)(b*NN + j)*INNERD + h*DH) >> 2;
                s_k4[j*KV4 + d4i] = ((const float4*)g_kbe)[goff + d4i];
                s_v4[j*KV4 + d4i] = ((const float4*)g_vbe)[goff + d4i];
            }
            if (tid < ITILE*16) {
                int il = tid >> 4, d4i = tid & 15;
                s_q4[il*16 + d4i] =
                    ((const float4*)g_q)[(((size_t)(b*NN + it*ITILE + il)*INNERD + h*DH) >> 2) + d4i];
            }
            __syncthreads();

            // qWe: warp il computes 3 dots (warp-parallel)
            {
                int il = wid;
                const float* qf = (const float*)&s_q4[il*16];
                float q0 = qf[lane], q1 = qf[lane + 32];
                #pragma unroll
                for (int c = 0; c < 3; c++) {
                    float w0 = __ldg(&We_l[c*INNERD + h*DH + lane]);
                    float w1 = __ldg(&We_l[c*INNERD + h*DH + lane + 32]);
                    float s = warp_sum(fmaf(q0, w0, q1*w1));
                    if (lane == 0) s_qwe[il*3 + c] = s;
                }
            }
            __syncthreads();

            int rp = wid & 7, jh = wid >> 3;
            int i0 = 2*rp, i1 = i0 + 1;
            int gi0 = it*ITILE + i0;
            int jbase = jh*64;

            // hoist edges
            float ev[2][2][3];
            #pragma unroll
            for (int r = 0; r < 2; r++)
                #pragma unroll
                for (int jt = 0; jt < 2; jt++) {
                    int j = jbase + 32*jt + lane;
                    const float* ep = &g_edges[((size_t)(b*NN + gi0 + r)*NN + j)*3];
                    ev[r][jt][0] = __ldg(&ep[0]);
                    ev[r][jt][1] = __ldg(&ep[1]);
                    ev[r][jt][2] = __ldg(&ep[2]);
                }

            // q·k: each k LDS feeds 2 rows
            u64 a2[2][2] = {{0,0},{0,0}};
            const ulonglong2* q0p = (const ulonglong2*)(s_q4 + i0*16);
            const ulonglong2* q1p = (const ulonglong2*)(s_q4 + i1*16);
            #pragma unroll 4
            for (int d4i = 0; d4i < 16; d4i++) {
                ulonglong2 q0 = q0p[d4i];
                ulonglong2 q1 = q1p[d4i];
                #pragma unroll
                for (int jt = 0; jt < 2; jt++) {
                    ulonglong2 k2 = *(const ulonglong2*)(s_k4 + (jbase + 32*jt + lane)*KV4 + d4i);
                    fma2(a2[0][jt], q0.x, k2.x); fma2(a2[0][jt], q0.y, k2.y);
                    fma2(a2[1][jt], q1.x, k2.x); fma2(a2[1][jt], q1.y, k2.y);
                }
            }
            float acc[2][2];
            #pragma unroll
            for (int r = 0; r < 2; r++) {
                float qw0 = s_qwe[(i0+r)*3+0], qw1 = s_qwe[(i0+r)*3+1], qw2 = s_qwe[(i0+r)*3+2];
                #pragma unroll
                for (int jt = 0; jt < 2; jt++) {
                    float2 f = upk(a2[r][jt]);
                    acc[r][jt] = (f.x + f.y
                        + ev[r][jt][0]*qw0 + ev[r][jt][1]*qw1 + ev[r][jt][2]*qw2) * SCALE;
                }
            }

            // cross-warp max
            float pm0 = warp_max(fmaxf(acc[0][0], acc[0][1]));
            float pm1 = warp_max(fmaxf(acc[1][0], acc[1][1]));
            if (lane == 0) { s_m[i0*2 + jh] = pm0; s_m[i1*2 + jh] = pm1; }
            __syncthreads();
            float m0 = fmaxf(s_m[i0*2+0], s_m[i0*2+1]);
            float m1 = fmaxf(s_m[i1*2+0], s_m[i1*2+1]);

            float p00 = __expf(acc[0][0] - m0), p01 = __expf(acc[0][1] - m0);
            float p10 = __expf(acc[1][0] - m1), p11 = __expf(acc[1][1] - m1);
            s_p2[i0*NN + jbase + lane]      = pk2(p00);
            s_p2[i0*NN + jbase + 32 + lane] = pk2(p01);
            s_p2[i1*NN + jbase + lane]      = pk2(p10);
            s_p2[i1*NN + jbase + 32 + lane] = pk2(p11);

            float sum0 = warp_sum(p00 + p01);
            float sum1 = warp_sum(p10 + p11);
            float sc00 = warp_sum(fmaf(p00, ev[0][0][0], p01*ev[0][1][0]));
            float sc01 = warp_sum(fmaf(p00, ev[0][0][1], p01*ev[0][1][1]));
            float sc02 = warp_sum(fmaf(p00, ev[0][0][2], p01*ev[0][1][2]));
            float sc10 = warp_sum(fmaf(p10, ev[1][0][0], p11*ev[1][1][0]));
            float sc11 = warp_sum(fmaf(p10, ev[1][0][1], p11*ev[1][1][1]));
            float sc12 = warp_sum(fmaf(p10, ev[1][0][2], p11*ev[1][1][2]));
            if (lane == 0) {
                s_s[i0*2 + jh] = sum0;  s_s[i1*2 + jh] = sum1;
                s_scp[(i0*2 + jh)*3 + 0] = sc00;
                s_scp[(i0*2 + jh)*3 + 1] = sc01;
                s_scp[(i0*2 + jh)*3 + 2] = sc02;
                s_scp[(i1*2 + jh)*3 + 0] = sc10;
                s_scp[(i1*2 + jh)*3 + 1] = sc11;
                s_scp[(i1*2 + jh)*3 + 2] = sc12;
            }
            __syncwarp();

            // pv: each v LDS feeds 2 rows
            int d4i = lane & 15, jsub = lane >> 4;
            u64 o00 = 0, o01 = 0, o10 = 0, o11 = 0;
            int jst = jbase + jsub*32;
            #pragma unroll 4
            for (int t = 0; t < 32; t++) {
                int j = jst + t;
                ulonglong2 v2 = *(const ulonglong2*)(s_v4 + j*KV4 + d4i);
                u64 pj0 = s_p2[i0*NN + j];
                u64 pj1 = s_p2[i1*NN + j];
                fma2(o00, pj0, v2.x); fma2(o01, pj0, v2.y);
                fma2(o10, pj1, v2.x); fma2(o11, pj1, v2.y);
            }
            float2 f00 = upk(o00), f01 = upk(o01), f10 = upk(o10), f11 = upk(o11);
            f00.x += __shfl_xor_sync(0xffffffffu, f00.x, 16);
            f00.y += __shfl_xor_sync(0xffffffffu, f00.y, 16);
            f01.x += __shfl_xor_sync(0xffffffffu, f01.x, 16);
            f01.y += __shfl_xor_sync(0xffffffffu, f01.y, 16);
            f10.x += __shfl_xor_sync(0xffffffffu, f10.x, 16);
            f10.y += __shfl_xor_sync(0xffffffffu, f10.y, 16);
            f11.x += __shfl_xor_sync(0xffffffffu, f11.x, 16);
            f11.y += __shfl_xor_sync(0xffffffffu, f11.y, 16);
            if (jsub == 0) {
                s_pv[((jh*8 + rp)*2 + 0)*16 + d4i] = make_float4(f00.x, f00.y, f01.x, f01.y);
                s_pv[((jh*8 + rp)*2 + 1)*16 + d4i] = make_float4(f10.x, f10.y, f11.x, f11.y);
            }
            __syncthreads();

            // epilogue: 256 threads, (row i, d4)
            if (tid < 256) {
                int i = tid >> 4;
                int dd = tid & 15;
                float4 A = s_pv[((0*8 + (i>>1))*2 + (i&1))*16 + dd];
                float4 Bv = s_pv[((1*8 + (i>>1))*2 + (i&1))*16 + dd];
                float inv = 1.f / (s_s[i*2+0] + s_s[i*2+1]);
                float4 o = make_float4((A.x+Bv.x)*inv, (A.y+Bv.y)*inv,
                                       (A.z+Bv.z)*inv, (A.w+Bv.w)*inv);
                #pragma unroll
                for (int c = 0; c < 3; c++) {
                    float scv = (s_scp[(i*2+0)*3 + c] + s_scp[(i*2+1)*3 + c]) * inv;
                    float4 w4 = __ldg((const float4*)(We_l + c*INNERD + h*DH + dd*4));
                    o.x = fmaf(scv, w4.x, o.x); o.y = fmaf(scv, w4.y, o.y);
                    o.z = fmaf(scv, w4.z, o.z); o.w = fmaf(scv, w4.w, o.w);
                }
                *(float4*)&g_ao[(size_t)(b*NN + it*ITILE + i)*INNERD + h*DH + dd*4] = o;
            }
        }
        gbar();

        // ======== phase C: Wo+gate1+LN2+FF+gate2, 128 blocks x 2 rows, f32x2 ===
        {
            const float* Wo_l  = Wo  + (size_t)l*INNERD*DIMF;
            const float* bo_l  = bo  + (size_t)l*DIMF;
            const float* Wg1_l = Wg1 + (size_t)l*3*DIMF;
            const float* g2l   = ln2g + (size_t)l*DIMF;
            const float* b2l   = ln2b + (size_t)l*DIMF;
            const float* W1_l  = W1  + (size_t)l*DIMF*4*DIMF;
            const float* b1_l  = b1  + (size_t)l*4*DIMF;
            const float* W2_l  = W2  + (size_t)l*4*DIMF*DIMF;
            const float* b2_l  = b2  + (size_t)l*DIMF;
            const float* Wg2_l = Wg2 + (size_t)l*3*DIMF;

            {
                u64*   s_d    = (u64*)pool;             // [512][2] dup ao / h1
                u64*   s_redU = s_d + 1024;             // 2048 u64
                u64*   s_lnD  = s_redU + 2048;          // [128][2]
                float* s_x    = (float*)(s_lnD + 256);  // [2][128]
                float* s_res  = s_x + 256;              // [2][128]

                int row0 = bid * 2;

                // stage ao duplicated [k][r]
                for (int idx = tid; idx < 2*INNERD; idx += NTHR) {
                    int r = idx >> 9, k = idx & 511;
                    s_d[k*2 + r] = pk2(g_ao[(size_t)(row0 + r)*INNERD + k]);
                }
                if (tid < 2*DIMF)
                    s_res[tid] = g_nodes[(row0 + (tid >> 7))*DIMF + (tid & 127)];
                __syncthreads();

                // ---- GEMM1: x = ao @ Wo : 16 kg x 32 iters, f32x2 -------------
                {
                    int cp = tid & 31, kg = tid >> 5;
                    u64 a00=0,a01=0,a10=0,a11=0;
                    int k0 = kg * 32;
                    #pragma unroll 16
                    for (int k = k0; k < k0 + 32; k++) {
                        ulonglong2 w2 = __ldg((const ulonglong2*)(Wo_l + (size_t)k*DIMF + cp*4));
                        ulonglong2 x01 = *(const ulonglong2*)&s_d[k*2];
                        fma2(a00, w2.x, x01.x); fma2(a01, w2.y, x01.x);
                        fma2(a10, w2.x, x01.y); fma2(a11, w2.y, x01.y);
                    }
                    int base = kg*128 + cp*4;
                    *(ulonglong2*)&s_redU[base + 0] = make_ulonglong2(a00, a01);
                    *(ulonglong2*)&s_redU[base + 2] = make_ulonglong2(a10, a11);
                }
                __syncthreads();
                if (tid < 128) {
                    float sx = 0.f, sy = 0.f;
                    #pragma unroll
                    for (int kg = 0; kg < 16; kg++) {
                        float2 pv = upk(s_redU[kg*128 + tid]);
                        sx += pv.x; sy += pv.y;
                    }
                    int cp = tid >> 2, idx2 = tid & 3, r = idx2 >> 1, p = idx2 & 1;
                    int c0 = cp*4 + p*2;
                    s_x[r*DIMF + c0]     = sx + __ldg(&bo_l[c0]);
                    s_x[r*DIMF + c0 + 1] = sy + __ldg(&bo_l[c0 + 1]);
                }
                __syncthreads();

                // ---- gate1 + LN2 (warp per row) -------------------------------
                if (wid < 2) {
                    int r = wid;
                    float xv[4], rv[4], pg = 0.f;
                    #pragma unroll
                    for (int q = 0; q < 4; q++) {
                        int c = lane + 32*q;
                        xv[q] = s_x[r*DIMF + c];
                        rv[q] = s_res[r*DIMF + c];
                        pg += xv[q]*__ldg(&Wg1_l[c]) + rv[q]*__ldg(&Wg1_l[DIMF + c])
                            + (xv[q]-rv[q])*__ldg(&Wg1_l[2*DIMF + c]);
                    }
                    float gs = warp_sum(pg);
                    float g1v = 1.f / (1.f + expf(-gs));
                    float n1[4], msum = 0.f;
                    #pragma unroll
                    for (int q = 0; q < 4; q++) { n1[q] = xv[q]*g1v + rv[q]*(1.f - g1v); msum += n1[q]; }
                    float mean = warp_sum(msum) * (1.f/DIMF);
                    float vsum = 0.f;
                    #pragma unroll
                    for (int q = 0; q < 4; q++) { float d = n1[q]-mean; vsum += d*d; }
                    float rstd = rsqrtf(warp_sum(vsum) * (1.f/DIMF) + 1e-5f);
                    #pragma unroll
                    for (int q = 0; q < 4; q++) {
                        int c = lane + 32*q;
                        s_res[r*DIMF + c] = n1[q];
                        s_lnD[c*2 + r] = pk2((n1[q]-mean)*rstd*__ldg(&g2l[c]) + __ldg(&b2l[c]));
                    }
                }
                __syncthreads();

                // ---- GEMM2: h1 = gelu(xn @ W1 + b1) : 4 kg x 32 iters ---------
                {
                    int cp = tid & 127, kg = tid >> 7;
                    u64 a00=0,a01=0,a10=0,a11=0;
                    int k0 = kg * 32;
                    #pragma unroll 16
                    for (int k = k0; k < k0 + 32; k++) {
                        ulonglong2 w2 = __ldg((const ulonglong2*)(W1_l + (size_t)k*INNERD + cp*4));
                        ulonglong2 x01 = *(const ulonglong2*)&s_lnD[k*2];
                        fma2(a00, w2.x, x01.x); fma2(a01, w2.y, x01.x);
                        fma2(a10, w2.x, x01.y); fma2(a11, w2.y, x01.y);
                    }
                    int base = kg*512 + cp*4;
                    *(ulonglong2*)&s_redU[base + 0] = make_ulonglong2(a00, a01);
                    *(ulonglong2*)&s_redU[base + 2] = make_ulonglong2(a10, a11);
                }
                __syncthreads();
                {
                    int u = tid;   // 512 final u64s
                    float sx = 0.f, sy = 0.f;
                    #pragma unroll
                    for (int kg = 0; kg < 4; kg++) {
                        float2 pv = upk(s_redU[kg*512 + u]);
                        sx += pv.x; sy += pv.y;
                    }
                    int cp = u >> 2, idx2 = u & 3, r = idx2 >> 1, p = idx2 & 1;
                    int c0 = cp*4 + p*2;
                    s_d[(c0    )*2 + r] = pk2(gelu_exact(sx + __ldg(&b1_l[c0])));
                    s_d[(c0 + 1)*2 + r] = pk2(gelu_exact(sy + __ldg(&b1_l[c0 + 1])));
                }
                __syncthreads();

                // ---- GEMM3: ff = h1 @ W2 : 16 kg x 32 iters -------------------
                {
                    int cp = tid & 31, kg = tid >> 5;
                    u64 a00=0,a01=0,a10=0,a11=0;
                    int k0 = kg * 32;
                    #pragma unroll 16
                    for (int k = k0; k < k0 + 32; k++) {
                        ulonglong2 w2 = __ldg((const ulonglong2*)(W2_l + (size_t)k*DIMF + cp*4));
                        ulonglong2 x01 = *(const ulonglong2*)&s_d[k*2];
                        fma2(a00, w2.x, x01.x); fma2(a01, w2.y, x01.x);
                        fma2(a10, w2.x, x01.y); fma2(a11, w2.y, x01.y);
                    }
                    int base = kg*128 + cp*4;
                    *(ulonglong2*)&s_redU[base + 0] = make_ulonglong2(a00, a01);
                    *(ulonglong2*)&s_redU[base + 2] = make_ulonglong2(a10, a11);
                }
                __syncthreads();
                if (tid < 128) {
                    float sx = 0.f, sy = 0.f;
                    #pragma unroll
                    for (int kg = 0; kg < 16; kg++) {
                        float2 pv = upk(s_redU[kg*128 + tid]);
                        sx += pv.x; sy += pv.y;
                    }
                    int cp = tid >> 2, idx2 = tid & 3, r = idx2 >> 1, p = idx2 & 1;
                    int c0 = cp*4 + p*2;
                    s_x[r*DIMF + c0]     = sx + __ldg(&b2_l[c0]);
                    s_x[r*DIMF + c0 + 1] = sy + __ldg(&b2_l[c0 + 1]);
                }
                __syncthreads();

                // ---- gate2 + write back ---------------------------------------
                if (wid < 2) {
                    int r = wid;
                    float fv[4], rv[4], pg = 0.f;
                    #pragma unroll
                    for (int q = 0; q < 4; q++) {
                        int c = lane + 32*q;
                        fv[q] = s_x[r*DIMF + c];
                        rv[q] = s_res[r*DIMF + c];
                        pg += fv[q]*__ldg(&Wg2_l[c]) + rv[q]*__ldg(&Wg2_l[DIMF + c])
                            + (fv[q]-rv[q])*__ldg(&Wg2_l[2*DIMF + c]);
                    }
                    float gs = warp_sum(pg);
                    float g2v = 1.f / (1.f + expf(-gs));
                    #pragma unroll
                    for (int q = 0; q < 4; q++) {
                        int c = lane + 32*q;
                        g_nodes[(row0 + r)*DIMF + c] = fv[q]*g2v + rv[q]*(1.f - g2v);
                    }
                }
            }
        }
        gbar();
    }

    // ---------------- final reduce (block 0) -----------------------------------
    if (bid == 0) {
        float* sred = (float*)pool;
        float acc = 0.f;
        for (int r = wid; r < BB*NN; r += 16) {
            float4 x = *(const float4*)&g_nodes[r*DIMF + lane*4];
            float4 w = *(const float4*)&Wlin[lane*4];
            acc += x.x*w.x + x.y*w.y + x.z*w.z + x.w*w.w;
        }
        acc = warp_sum(acc);
        if (lane == 0) sred[wid] = acc;
        __syncthreads();
        if (tid == 0) {
            float t = 0.f;
            #pragma unroll
            for (int w = 0; w < 16; w++) t += sred[w];
            out[0] = t + (float)(BB*NN) * blin[0];
        }
    }
}

// ---------------- launch -------------------------------------------------------
extern "C" void kernel_launch(void* const* d_in, const int* in_sizes, int n_in,
                              void* d_out, int out_size)
{
    const int*   indices  = (const int*)  d_in[0];
    const float* coords   = (const float*)d_in[1];
    const int*   bonds    = (const int*)  d_in[2];
    const float* noise    = (const float*)d_in[3];
    const float* atom_emb = (const float*)d_in[4];
    const float* ln1_g    = (const float*)d_in[5];
    const float* ln1_b    = (const float*)d_in[6];
    const float* Wq       = (const float*)d_in[7];
    const float* bq       = (const float*)d_in[8];
    const float* Wkv      = (const float*)d_in[9];
    const float* bkv      = (const float*)d_in[10];
    const float* We_      = (const float*)d_in[11];
    const float* be       = (const float*)d_in[12];
    const float* Wo       = (const float*)d_in[13];
    const float* bo       = (const float*)d_in[14];
    const float* Wg1      = (const float*)d_in[15];
    const float* ln2g     = (const float*)d_in[16];
    const float* ln2b     = (const float*)d_in[17];
    const float* W1       = (const float*)d_in[18];
    const float* b1       = (const float*)d_in[19];
    const float* W2       = (const float*)d_in[20];
    const float* b2       = (const float*)d_in[21];
    const float* Wg2      = (const float*)d_in[22];
    const float* Wlin     = (const float*)d_in[23];
    const float* blin     = (const float*)d_in[24];

    cudaFuncSetAttribute(k_net, cudaFuncAttributeMaxDynamicSharedMemorySize,
                         POOL_BYTES);

    k_net<<<GRIDN, NTHR, POOL_BYTES>>>(
        indices, coords, bonds, noise, atom_emb,
        ln1_g, ln1_b, Wq, bq, Wkv, bkv, We_, be, Wo, bo, Wg1,
        ln2g, ln2b, W1, b1, W2, b2, Wg2, Wlin, blin,
        (float*)d_out);
}

// round 14
// speedup vs baseline: 1.0430x; 1.0430x over previous
#include <cuda_runtime.h>
#include <math.h>

#define BB     2
#define NN     128
#define EB     160
#define DEPTHL 6
#define NHEADS 8
#define DH     64
#define INNERD 512
#define DIMF   128
#define NF     127
#define SCALE  0.125f  /* 64^-0.5 */

#define GRIDN  128
#define NTHR   512

typedef unsigned long long u64;

// ---------------- f32x2 helpers -----------------------------------------------
__device__ __forceinline__ u64 pk2(float x) {
    u64 r; asm("mov.b64 %0, {%1,%1};" : "=l"(r) : "f"(x)); return r;
}
__device__ __forceinline__ void fma2(u64 &d, u64 a, u64 b) {
    asm("fma.rn.f32x2 %0, %1, %2, %3;" : "=l"(d) : "l"(a), "l"(b), "l"(d));
}
__device__ __forceinline__ float2 upk(u64 v) {
    float2 f; asm("mov.b64 {%0,%1}, %2;" : "=f"(f.x), "=f"(f.y) : "l"(v)); return f;
}

// ---------------- scratch (static device globals; no allocation) --------------
__device__ float g_nodes[BB*NN*DIMF];
__device__ float g_edges[BB*NN*NN*3];
__device__ float g_q   [BB*NN*INNERD];
__device__ float g_kbe [BB*NN*INNERD];
__device__ float g_vbe [BB*NN*INNERD];
__device__ float g_ao  [BB*NN*INNERD];

__device__ unsigned g_cnt = 0;
__device__ unsigned g_gen = 0;

// ---------------- grid barrier (all GRIDN blocks resident) --------------------
__device__ __forceinline__ void gbar() {
    __syncthreads();
    if (threadIdx.x == 0) {
        volatile unsigned* vg = &g_gen;
        unsigned gen = *vg;
        __threadfence();
        if (atomicAdd(&g_cnt, 1u) == GRIDN - 1) {
            atomicExch(&g_cnt, 0u);
            __threadfence();
            atomicAdd(&g_gen, 1u);
        } else {
            while (*vg == gen) { }
        }
        __threadfence();
    }
    __syncthreads();
}

// ---------------- warp helpers -------------------------------------------------
__device__ __forceinline__ float warp_sum(float v) {
    #pragma unroll
    for (int off = 16; off > 0; off >>= 1)
        v += __shfl_xor_sync(0xffffffffu, v, off);
    return v;
}
__device__ __forceinline__ float warp_max(float v) {
    #pragma unroll
    for (int off = 16; off > 0; off >>= 1)
        v = fmaxf(v, __shfl_xor_sync(0xffffffffu, v, off));
    return v;
}
__device__ __forceinline__ float gelu_exact(float u) {
    return 0.5f * u * (1.f + erff(u * 0.70710678118654752f));
}

#define RT_ROWS 16
#define ITILE 16
#define KV4   17
#define XDS   19   /* u64 stride of dup LN buffer: 2-way STS banks */
// B-phase pool: k 34816 + v 34816 + q 4096 + p2 16384 + qwe 192
//             + s_m 128 + s_s 128 + s_scp 384 + s_pv 8192 = 99136
#define POOL_BYTES 99328

// ================================================================================
__global__ void __launch_bounds__(NTHR, 1) k_net(
    const int* __restrict__ indices, const float* __restrict__ coords,
    const int* __restrict__ bonds,   const float* __restrict__ noise,
    const float* __restrict__ atom_emb,
    const float* __restrict__ ln1_g, const float* __restrict__ ln1_b,
    const float* __restrict__ Wq,  const float* __restrict__ bq,
    const float* __restrict__ Wkv, const float* __restrict__ bkv,
    const float* __restrict__ We_, const float* __restrict__ be,
    const float* __restrict__ Wo,  const float* __restrict__ bo,
    const float* __restrict__ Wg1,
    const float* __restrict__ ln2g, const float* __restrict__ ln2b,
    const float* __restrict__ W1,  const float* __restrict__ b1,
    const float* __restrict__ W2,  const float* __restrict__ b2,
    const float* __restrict__ Wg2,
    const float* __restrict__ Wlin, const float* __restrict__ blin,
    float* __restrict__ out)
{
    extern __shared__ __align__(16) char pool[];
    int bid = blockIdx.x, tid = threadIdx.x;
    int wid = tid >> 5, lane = tid & 31;

    // ---------------- phase 0: node init + edge zero ---------------------------
    {
        int idx = bid*NTHR + tid;
        if (idx < BB*NN*DIMF) {
            int f = idx & 127, bn = idx >> 7;
            g_nodes[idx] = (f < NF) ? atom_emb[indices[bn]*NF + f] : noise[0];
        }
        if (idx < (BB*NN*NN*3)/4)
            ((float4*)g_edges)[idx] = make_float4(0.f, 0.f, 0.f, 0.f);
    }
    gbar();

    // ---------------- phase 0b: edge scatter (block 0) -------------------------
    if (bid == 0) {
        int* sb = (int*)pool;
        for (int t = tid; t < EB*2; t += NTHR) sb[t] = bonds[t];
        __syncthreads();
        if (tid < EB) {
            int i = sb[2*tid], j = sb[2*tid+1];
            bool laterSame = false, revExists = false;
            #pragma unroll 4
            for (int e = 0; e < EB; e++) {
                int ie = sb[2*e], je = sb[2*e+1];
                if (e > tid && ie == i && je == j) laterSame = true;
                if (ie == j && je == i)            revExists = true;
            }
            bool w2 = !laterSame;
            bool w1 = !laterSame && !revExists;
            if (w1 || w2) {
                for (int b = 0; b < BB; b++) {
                    float d0 = coords[(b*NN+i)*3+0] - coords[(b*NN+j)*3+0];
                    float d1 = coords[(b*NN+i)*3+1] - coords[(b*NN+j)*3+1];
                    float d2 = coords[(b*NN+i)*3+2] - coords[(b*NN+j)*3+2];
                    if (w2) {
                        size_t o = ((size_t)(b*NN+j)*NN + i)*3;
                        g_edges[o+0] = -d0; g_edges[o+1] = -d1; g_edges[o+2] = -d2;
                    }
                    if (w1) {
                        size_t o = ((size_t)(b*NN+i)*NN + j)*3;
                        g_edges[o+0] = d0; g_edges[o+1] = d1; g_edges[o+2] = d2;
                    }
                }
            }
        }
    }
    gbar();

    // ---------------- layers ---------------------------------------------------
    for (int l = 0; l < DEPTHL; l++) {
        // ======== phase A: LN1 + Q/KV proj, f32x2 (blocks 0..95, 512 thr) ======
        {
            const float* ln_g  = ln1_g + l*DIMF;
            const float* ln_b  = ln1_b + l*DIMF;
            const float* Wq_l  = Wq  + (size_t)l*DIMF*INNERD;
            const float* bq_l  = bq  + (size_t)l*INNERD;
            const float* Wkv_l = Wkv + (size_t)l*DIMF*2*INNERD;
            const float* bkv_l = bkv + (size_t)l*2*INNERD;
            const float* be_l  = be  + (size_t)l*INNERD;

            if (bid < 96) {
                u64* s_xd = (u64*)pool;            // [128][XDS] dup
                int rowTile = bid / 6, ct = bid % 6, r0 = rowTile * RT_ROWS;

                // LN: warp per row; d = q*32 + lane (coalesced LDG, 2-way STS)
                {
                    int r = wid;
                    float xq[4];
                    #pragma unroll
                    for (int q = 0; q < 4; q++)
                        xq[q] = g_nodes[(r0+r)*DIMF + q*32 + lane];
                    float s = xq[0] + xq[1] + xq[2] + xq[3];
                    float mean = warp_sum(s) * (1.f/DIMF);
                    float v = 0.f;
                    #pragma unroll
                    for (int q = 0; q < 4; q++) { xq[q] -= mean; v += xq[q]*xq[q]; }
                    float rstd = rsqrtf(warp_sum(v) * (1.f/DIMF) + 1e-5f);
                    #pragma unroll
                    for (int q = 0; q < 4; q++) {
                        int d = q*32 + lane;
                        s_xd[d*XDS + r] = pk2(xq[q] * rstd * __ldg(&ln_g[d]) + __ldg(&ln_b[d]));
                    }
                }
                __syncthreads();

                // projection: thread = 4 cols (2 f32x2 pairs) x 2 rows
                int quad = tid & 63;
                int rg   = tid >> 6;            // 0..7
                int col  = ct*256 + quad*4;
                int rA   = rg*2;

                const float* Wp;
                int stride, region, rcol;
                if (col < 512) { Wp = Wq_l + col; stride = INNERD; region = 0; rcol = col; }
                else {
                    int ck = col - 512;
                    Wp = Wkv_l + ck; stride = 2*INNERD;
                    if (ck < 512) { region = 1; rcol = ck; }
                    else          { region = 2; rcol = ck - 512; }
                }

                u64 aA0=0, aA1=0, aB0=0, aB1=0;
                #pragma unroll 8
                for (int d = 0; d < DIMF; d++) {
                    ulonglong2 w2 = __ldg((const ulonglong2*)(Wp + (size_t)d*stride));
                    u64 xA = s_xd[d*XDS + rA];
                    u64 xB = s_xd[d*XDS + rA + 1];
                    fma2(aA0, w2.x, xA); fma2(aA1, w2.y, xA);
                    fma2(aB0, w2.x, xB); fma2(aB1, w2.y, xB);
                }

                float4 bias;
                if (region == 0) bias = __ldg((const float4*)(bq_l + rcol));
                else {
                    float4 bk = __ldg((const float4*)(bkv_l + (region==1 ? rcol : rcol+512)));
                    float4 bv = __ldg((const float4*)(be_l + rcol));
                    bias = make_float4(bk.x+bv.x, bk.y+bv.y, bk.z+bv.z, bk.w+bv.w);
                }
                float* dst = (region==0) ? g_q : (region==1) ? g_kbe : g_vbe;
                float2 fA0 = upk(aA0), fA1 = upk(aA1), fB0 = upk(aB0), fB1 = upk(aB1);
                float4 oA = make_float4(fA0.x+bias.x, fA0.y+bias.y, fA1.x+bias.z, fA1.y+bias.w);
                float4 oB = make_float4(fB0.x+bias.x, fB0.y+bias.y, fB1.x+bias.z, fB1.y+bias.w);
                *(float4*)&dst[(size_t)(r0+rA  )*INNERD + rcol] = oA;
                *(float4*)&dst[(size_t)(r0+rA+1)*INNERD + rcol] = oB;
            }
        }
        gbar();

        // ======== phase B: attention (all 128 blocks, 512 thr) =================
        {
            const float* We_l = We_ + (size_t)l*3*INNERD;
            float4* s_k4  = (float4*)pool;               // [128][17]
            float4* s_v4  = s_k4 + NN*KV4;
            float4* s_q4  = s_v4 + NN*KV4;               // [16][16]
            u64*    s_p2  = (u64*)(s_q4 + ITILE*16);     // [16][128] unnorm exp
            float*  s_qwe = (float*)(s_p2 + ITILE*NN);   // [16][3]
            float*  s_m   = s_qwe + 48;                  // [16][2]
            float*  s_s   = s_m + 32;                    // [16][2]
            float*  s_scp = s_s + 32;                    // [16][2][3]
            float4* s_pv  = (float4*)(s_scp + 96);       // [2jh][8rp][2row][16d4]

            int b  = bid >> 6;
            int h  = (bid >> 3) & 7;
            int it = bid & 7;

            for (int idx = tid; idx < NN*16; idx += NTHR) {
                int j = idx >> 4, d4i = idx & 15;
                size_t goff = ((size_t)(b*NN + j)*INNERD + h*DH) >> 2;
                s_k4[j*KV4 + d4i] = ((const float4*)g_kbe)[goff + d4i];
                s_v4[j*KV4 + d4i] = ((const float4*)g_vbe)[goff + d4i];
            }
            if (tid < ITILE*16) {
                int il = tid >> 4, d4i = tid & 15;
                s_q4[il*16 + d4i] =
                    ((const float4*)g_q)[(((size_t)(b*NN + it*ITILE + il)*INNERD + h*DH) >> 2) + d4i];
            }
            __syncthreads();

            // qWe: warp il computes 3 dots (warp-parallel)
            {
                int il = wid;
                const float* qf = (const float*)&s_q4[il*16];
                float q0 = qf[lane], q1 = qf[lane + 32];
                #pragma unroll
                for (int c = 0; c < 3; c++) {
                    float w0 = __ldg(&We_l[c*INNERD + h*DH + lane]);
                    float w1 = __ldg(&We_l[c*INNERD + h*DH + lane + 32]);
                    float s = warp_sum(fmaf(q0, w0, q1*w1));
                    if (lane == 0) s_qwe[il*3 + c] = s;
                }
            }
            __syncthreads();

            int rp = wid & 7, jh = wid >> 3;
            int i0 = 2*rp, i1 = i0 + 1;
            int gi0 = it*ITILE + i0;
            int jbase = jh*64;

            // hoist edges
            float ev[2][2][3];
            #pragma unroll
            for (int r = 0; r < 2; r++)
                #pragma unroll
                for (int jt = 0; jt < 2; jt++) {
                    int j = jbase + 32*jt + lane;
                    const float* ep = &g_edges[((size_t)(b*NN + gi0 + r)*NN + j)*3];
                    ev[r][jt][0] = __ldg(&ep[0]);
                    ev[r][jt][1] = __ldg(&ep[1]);
                    ev[r][jt][2] = __ldg(&ep[2]);
                }

            // q·k: each k LDS feeds 2 rows
            u64 a2[2][2] = {{0,0},{0,0}};
            const ulonglong2* q0p = (const ulonglong2*)(s_q4 + i0*16);
            const ulonglong2* q1p = (const ulonglong2*)(s_q4 + i1*16);
            #pragma unroll 4
            for (int d4i = 0; d4i < 16; d4i++) {
                ulonglong2 q0 = q0p[d4i];
                ulonglong2 q1 = q1p[d4i];
                #pragma unroll
                for (int jt = 0; jt < 2; jt++) {
                    ulonglong2 k2 = *(const ulonglong2*)(s_k4 + (jbase + 32*jt + lane)*KV4 + d4i);
                    fma2(a2[0][jt], q0.x, k2.x); fma2(a2[0][jt], q0.y, k2.y);
                    fma2(a2[1][jt], q1.x, k2.x); fma2(a2[1][jt], q1.y, k2.y);
                }
            }
            float acc[2][2];
            #pragma unroll
            for (int r = 0; r < 2; r++) {
                float qw0 = s_qwe[(i0+r)*3+0], qw1 = s_qwe[(i0+r)*3+1], qw2 = s_qwe[(i0+r)*3+2];
                #pragma unroll
                for (int jt = 0; jt < 2; jt++) {
                    float2 f = upk(a2[r][jt]);
                    acc[r][jt] = (f.x + f.y
                        + ev[r][jt][0]*qw0 + ev[r][jt][1]*qw1 + ev[r][jt][2]*qw2) * SCALE;
                }
            }

            // cross-warp max
            float pm0 = warp_max(fmaxf(acc[0][0], acc[0][1]));
            float pm1 = warp_max(fmaxf(acc[1][0], acc[1][1]));
            if (lane == 0) { s_m[i0*2 + jh] = pm0; s_m[i1*2 + jh] = pm1; }
            __syncthreads();
            float m0 = fmaxf(s_m[i0*2+0], s_m[i0*2+1]);
            float m1 = fmaxf(s_m[i1*2+0], s_m[i1*2+1]);

            float p00 = __expf(acc[0][0] - m0), p01 = __expf(acc[0][1] - m0);
            float p10 = __expf(acc[1][0] - m1), p11 = __expf(acc[1][1] - m1);
            s_p2[i0*NN + jbase + lane]      = pk2(p00);
            s_p2[i0*NN + jbase + 32 + lane] = pk2(p01);
            s_p2[i1*NN + jbase + lane]      = pk2(p10);
            s_p2[i1*NN + jbase + 32 + lane] = pk2(p11);

            float sum0 = warp_sum(p00 + p01);
            float sum1 = warp_sum(p10 + p11);
            float sc00 = warp_sum(fmaf(p00, ev[0][0][0], p01*ev[0][1][0]));
            float sc01 = warp_sum(fmaf(p00, ev[0][0][1], p01*ev[0][1][1]));
            float sc02 = warp_sum(fmaf(p00, ev[0][0][2], p01*ev[0][1][2]));
            float sc10 = warp_sum(fmaf(p10, ev[1][0][0], p11*ev[1][1][0]));
            float sc11 = warp_sum(fmaf(p10, ev[1][0][1], p11*ev[1][1][1]));
            float sc12 = warp_sum(fmaf(p10, ev[1][0][2], p11*ev[1][1][2]));
            if (lane == 0) {
                s_s[i0*2 + jh] = sum0;  s_s[i1*2 + jh] = sum1;
                s_scp[(i0*2 + jh)*3 + 0] = sc00;
                s_scp[(i0*2 + jh)*3 + 1] = sc01;
                s_scp[(i0*2 + jh)*3 + 2] = sc02;
                s_scp[(i1*2 + jh)*3 + 0] = sc10;
                s_scp[(i1*2 + jh)*3 + 1] = sc11;
                s_scp[(i1*2 + jh)*3 + 2] = sc12;
            }
            __syncwarp();

            // pv: each v LDS feeds 2 rows
            int d4i = lane & 15, jsub = lane >> 4;
            u64 o00 = 0, o01 = 0, o10 = 0, o11 = 0;
            int jst = jbase + jsub*32;
            #pragma unroll 4
            for (int t = 0; t < 32; t++) {
                int j = jst + t;
                ulonglong2 v2 = *(const ulonglong2*)(s_v4 + j*KV4 + d4i);
                u64 pj0 = s_p2[i0*NN + j];
                u64 pj1 = s_p2[i1*NN + j];
                fma2(o00, pj0, v2.x); fma2(o01, pj0, v2.y);
                fma2(o10, pj1, v2.x); fma2(o11, pj1, v2.y);
            }
            float2 f00 = upk(o00), f01 = upk(o01), f10 = upk(o10), f11 = upk(o11);
            f00.x += __shfl_xor_sync(0xffffffffu, f00.x, 16);
            f00.y += __shfl_xor_sync(0xffffffffu, f00.y, 16);
            f01.x += __shfl_xor_sync(0xffffffffu, f01.x, 16);
            f01.y += __shfl_xor_sync(0xffffffffu, f01.y, 16);
            f10.x += __shfl_xor_sync(0xffffffffu, f10.x, 16);
            f10.y += __shfl_xor_sync(0xffffffffu, f10.y, 16);
            f11.x += __shfl_xor_sync(0xffffffffu, f11.x, 16);
            f11.y += __shfl_xor_sync(0xffffffffu, f11.y, 16);
            if (jsub == 0) {
                s_pv[((jh*8 + rp)*2 + 0)*16 + d4i] = make_float4(f00.x, f00.y, f01.x, f01.y);
                s_pv[((jh*8 + rp)*2 + 1)*16 + d4i] = make_float4(f10.x, f10.y, f11.x, f11.y);
            }
            __syncthreads();

            // epilogue: 256 threads, (row i, d4)
            if (tid < 256) {
                int i = tid >> 4;
                int dd = tid & 15;
                float4 A = s_pv[((0*8 + (i>>1))*2 + (i&1))*16 + dd];
                float4 Bv = s_pv[((1*8 + (i>>1))*2 + (i&1))*16 + dd];
                float inv = 1.f / (s_s[i*2+0] + s_s[i*2+1]);
                float4 o = make_float4((A.x+Bv.x)*inv, (A.y+Bv.y)*inv,
                                       (A.z+Bv.z)*inv, (A.w+Bv.w)*inv);
                #pragma unroll
                for (int c = 0; c < 3; c++) {
                    float scv = (s_scp[(i*2+0)*3 + c] + s_scp[(i*2+1)*3 + c]) * inv;
                    float4 w4 = __ldg((const float4*)(We_l + c*INNERD + h*DH + dd*4));
                    o.x = fmaf(scv, w4.x, o.x); o.y = fmaf(scv, w4.y, o.y);
                    o.z = fmaf(scv, w4.z, o.z); o.w = fmaf(scv, w4.w, o.w);
                }
                *(float4*)&g_ao[(size_t)(b*NN + it*ITILE + i)*INNERD + h*DH + dd*4] = o;
            }
        }
        gbar();

        // ======== phase C: Wo+gate1+LN2+FF+gate2, 128 blocks x 2 rows, f32x2 ===
        {
            const float* Wo_l  = Wo  + (size_t)l*INNERD*DIMF;
            const float* bo_l  = bo  + (size_t)l*DIMF;
            const float* Wg1_l = Wg1 + (size_t)l*3*DIMF;
            const float* g2l   = ln2g + (size_t)l*DIMF;
            const float* b2l   = ln2b + (size_t)l*DIMF;
            const float* W1_l  = W1  + (size_t)l*DIMF*4*DIMF;
            const float* b1_l  = b1  + (size_t)l*4*DIMF;
            const float* W2_l  = W2  + (size_t)l*DIMF*4*DIMF;
            const float* b2_l  = b2  + (size_t)l*DIMF;
            const float* Wg2_l = Wg2 + (size_t)l*3*DIMF;

            {
                u64*   s_d    = (u64*)pool;             // [512][2] dup ao / h1
                u64*   s_redU = s_d + 1024;             // 2048 u64
                u64*   s_lnD  = s_redU + 2048;          // [128][2]
                float* s_x    = (float*)(s_lnD + 256);  // [2][128]
                float* s_res  = s_x + 256;              // [2][128]

                int row0 = bid * 2;

                // stage ao duplicated [k][r]
                for (int idx = tid; idx < 2*INNERD; idx += NTHR) {
                    int r = idx >> 9, k = idx & 511;
                    s_d[k*2 + r] = pk2(g_ao[(size_t)(row0 + r)*INNERD + k]);
                }
                if (tid < 2*DIMF)
                    s_res[tid] = g_nodes[(row0 + (tid >> 7))*DIMF + (tid & 127)];
                __syncthreads();

                // ---- GEMM1: x = ao @ Wo : 16 kg x 32 iters, f32x2 -------------
                {
                    int cp = tid & 31, kg = tid >> 5;
                    u64 a00=0,a01=0,a10=0,a11=0;
                    int k0 = kg * 32;
                    #pragma unroll 8
                    for (int k = k0; k < k0 + 32; k++) {
                        ulonglong2 w2 = __ldg((const ulonglong2*)(Wo_l + (size_t)k*DIMF + cp*4));
                        ulonglong2 x01 = *(const ulonglong2*)&s_d[k*2];
                        fma2(a00, w2.x, x01.x); fma2(a01, w2.y, x01.x);
                        fma2(a10, w2.x, x01.y); fma2(a11, w2.y, x01.y);
                    }
                    int base = kg*128 + cp*4;
                    *(ulonglong2*)&s_redU[base + 0] = make_ulonglong2(a00, a01);
                    *(ulonglong2*)&s_redU[base + 2] = make_ulonglong2(a10, a11);
                }
                __syncthreads();
                if (tid < 128) {
                    float sx = 0.f, sy = 0.f;
                    #pragma unroll
                    for (int kg = 0; kg < 16; kg++) {
                        float2 pv = upk(s_redU[kg*128 + tid]);
                        sx += pv.x; sy += pv.y;
                    }
                    int cp = tid >> 2, idx2 = tid & 3, r = idx2 >> 1, p = idx2 & 1;
                    int c0 = cp*4 + p*2;
                    s_x[r*DIMF + c0]     = sx + __ldg(&bo_l[c0]);
                    s_x[r*DIMF + c0 + 1] = sy + __ldg(&bo_l[c0 + 1]);
                }
                __syncthreads();

                // ---- gate1 + LN2 (warp per row) -------------------------------
                if (wid < 2) {
                    int r = wid;
                    float xv[4], rv[4], pg = 0.f;
                    #pragma unroll
                    for (int q = 0; q < 4; q++) {
                        int c = lane + 32*q;
                        xv[q] = s_x[r*DIMF + c];
                        rv[q] = s_res[r*DIMF + c];
                        pg += xv[q]*__ldg(&Wg1_l[c]) + rv[q]*__ldg(&Wg1_l[DIMF + c])
                            + (xv[q]-rv[q])*__ldg(&Wg1_l[2*DIMF + c]);
                    }
                    float gs = warp_sum(pg);
                    float g1v = 1.f / (1.f + expf(-gs));
                    float n1[4], msum = 0.f;
                    #pragma unroll
                    for (int q = 0; q < 4; q++) { n1[q] = xv[q]*g1v + rv[q]*(1.f - g1v); msum += n1[q]; }
                    float mean = warp_sum(msum) * (1.f/DIMF);
                    float vsum = 0.f;
                    #pragma unroll
                    for (int q = 0; q < 4; q++) { float d = n1[q]-mean; vsum += d*d; }
                    float rstd = rsqrtf(warp_sum(vsum) * (1.f/DIMF) + 1e-5f);
                    #pragma unroll
                    for (int q = 0; q < 4; q++) {
                        int c = lane + 32*q;
                        s_res[r*DIMF + c] = n1[q];
                        s_lnD[c*2 + r] = pk2((n1[q]-mean)*rstd*__ldg(&g2l[c]) + __ldg(&b2l[c]));
                    }
                }
                __syncthreads();

                // ---- GEMM2: h1 = gelu(xn @ W1 + b1) : 4 kg x 32 iters ---------
                {
                    int cp = tid & 127, kg = tid >> 7;
                    u64 a00=0,a01=0,a10=0,a11=0;
                    int k0 = kg * 32;
                    #pragma unroll 8
                    for (int k = k0; k < k0 + 32; k++) {
                        ulonglong2 w2 = __ldg((const ulonglong2*)(W1_l + (size_t)k*INNERD + cp*4));
                        ulonglong2 x01 = *(const ulonglong2*)&s_lnD[k*2];
                        fma2(a00, w2.x, x01.x); fma2(a01, w2.y, x01.x);
                        fma2(a10, w2.x, x01.y); fma2(a11, w2.y, x01.y);
                    }
                    int base = kg*512 + cp*4;
                    *(ulonglong2*)&s_redU[base + 0] = make_ulonglong2(a00, a01);
                    *(ulonglong2*)&s_redU[base + 2] = make_ulonglong2(a10, a11);
                }
                __syncthreads();
                {
                    int u = tid;   // 512 final u64s
                    float sx = 0.f, sy = 0.f;
                    #pragma unroll
                    for (int kg = 0; kg < 4; kg++) {
                        float2 pv = upk(s_redU[kg*512 + u]);
                        sx += pv.x; sy += pv.y;
                    }
                    int cp = u >> 2, idx2 = u & 3, r = idx2 >> 1, p = idx2 & 1;
                    int c0 = cp*4 + p*2;
                    s_d[(c0    )*2 + r] = pk2(gelu_exact(sx + __ldg(&b1_l[c0])));
                    s_d[(c0 + 1)*2 + r] = pk2(gelu_exact(sy + __ldg(&b1_l[c0 + 1])));
                }
                __syncthreads();

                // ---- GEMM3: ff = h1 @ W2 : 16 kg x 32 iters -------------------
                {
                    int cp = tid & 31, kg = tid >> 5;
                    u64 a00=0,a01=0,a10=0,a11=0;
                    int k0 = kg * 32;
                    #pragma unroll 8
                    for (int k = k0; k < k0 + 32; k++) {
                        ulonglong2 w2 = __ldg((const ulonglong2*)(W2_l + (size_t)k*DIMF + cp*4));
                        ulonglong2 x01 = *(const ulonglong2*)&s_d[k*2];
                        fma2(a00, w2.x, x01.x); fma2(a01, w2.y, x01.x);
                        fma2(a10, w2.x, x01.y); fma2(a11, w2.y, x01.y);
                    }
                    int base = kg*128 + cp*4;
                    *(ulonglong2*)&s_redU[base + 0] = make_ulonglong2(a00, a01);
                    *(ulonglong2*)&s_redU[base + 2] = make_ulonglong2(a10, a11);
                }
                __syncthreads();
                if (tid < 128) {
                    float sx = 0.f, sy = 0.f;
                    #pragma unroll
                    for (int kg = 0; kg < 16; kg++) {
                        float2 pv = upk(s_redU[kg*128 + tid]);
                        sx += pv.x; sy += pv.y;
                    }
                    int cp = tid >> 2, idx2 = tid & 3, r = idx2 >> 1, p = idx2 & 1;
                    int c0 = cp*4 + p*2;
                    s_x[r*DIMF + c0]     = sx + __ldg(&b2_l[c0]);
                    s_x[r*DIMF + c0 + 1] = sy + __ldg(&b2_l[c0 + 1]);
                }
                __syncthreads();

                // ---- gate2 + write back ---------------------------------------
                if (wid < 2) {
                    int r = wid;
                    float fv[4], rv[4], pg = 0.f;
                    #pragma unroll
                    for (int q = 0; q < 4; q++) {
                        int c = lane + 32*q;
                        fv[q] = s_x[r*DIMF + c];
                        rv[q] = s_res[r*DIMF + c];
                        pg += fv[q]*__ldg(&Wg2_l[c]) + rv[q]*__ldg(&Wg2_l[DIMF + c])
                            + (fv[q]-rv[q])*__ldg(&Wg2_l[2*DIMF + c]);
                    }
                    float gs = warp_sum(pg);
                    float g2v = 1.f / (1.f + expf(-gs));
                    #pragma unroll
                    for (int q = 0; q < 4; q++) {
                        int c = lane + 32*q;
                        g_nodes[(row0 + r)*DIMF + c] = fv[q]*g2v + rv[q]*(1.f - g2v);
                    }
                }
            }
        }
        gbar();
    }

    // ---------------- final reduce (block 0) -----------------------------------
    if (bid == 0) {
        float* sred = (float*)pool;
        float acc = 0.f;
        for (int r = wid; r < BB*NN; r += 16) {
            float4 x = *(const float4*)&g_nodes[r*DIMF + lane*4];
            float4 w = *(const float4*)&Wlin[lane*4];
            acc += x.x*w.x + x.y*w.y + x.z*w.z + x.w*w.w;
        }
        acc = warp_sum(acc);
        if (lane == 0) sred[wid] = acc;
        __syncthreads();
        if (tid == 0) {
            float t = 0.f;
            #pragma unroll
            for (int w = 0; w < 16; w++) t += sred[w];
            out[0] = t + (float)(BB*NN) * blin[0];
        }
    }
}

// ---------------- launch -------------------------------------------------------
extern "C" void kernel_launch(void* const* d_in, const int* in_sizes, int n_in,
                              void* d_out, int out_size)
{
    const int*   indices  = (const int*)  d_in[0];
    const float* coords   = (const float*)d_in[1];
    const int*   bonds    = (const int*)  d_in[2];
    const float* noise    = (const float*)d_in[3];
    const float* atom_emb = (const float*)d_in[4];
    const float* ln1_g    = (const float*)d_in[5];
    const float* ln1_b    = (const float*)d_in[6];
    const float* Wq       = (const float*)d_in[7];
    const float* bq       = (const float*)d_in[8];
    const float* Wkv      = (const float*)d_in[9];
    const float* bkv      = (const float*)d_in[10];
    const float* We_      = (const float*)d_in[11];
    const float* be       = (const float*)d_in[12];
    const float* Wo       = (const float*)d_in[13];
    const float* bo       = (const float*)d_in[14];
    const float* Wg1      = (const float*)d_in[15];
    const float* ln2g     = (const float*)d_in[16];
    const float* ln2b     = (const float*)d_in[17];
    const float* W1       = (const float*)d_in[18];
    const float* b1       = (const float*)d_in[19];
    const float* W2       = (const float*)d_in[20];
    const float* b2       = (const float*)d_in[21];
    const float* Wg2      = (const float*)d_in[22];
    const float* Wlin     = (const float*)d_in[23];
    const float* blin     = (const float*)d_in[24];

    cudaFuncSetAttribute(k_net, cudaFuncAttributeMaxDynamicSharedMemorySize,
                         POOL_BYTES);

    k_net<<<GRIDN, NTHR, POOL_BYTES>>>(
        indices, coords, bonds, noise, atom_emb,
        ln1_g, ln1_b, Wq, bq, Wkv, bkv, We_, be, Wo, bo, Wg1,
        ln2g, ln2b, W1, b1, W2, b2, Wg2, Wlin, blin,
        (float*)d_out);
}